// round 1
// baseline (speedup 1.0000x reference)
#include <cuda_runtime.h>

// Scratch accumulators (no device allocation allowed -> __device__ globals)
__device__ double g_accum[2];   // [0] = sum of squared diffs, [1] = sum over batch of (1 - s4/s2^2)

static constexpr int   B       = 256;
static constexpr int   H       = 512;
static constexpr long  N_ELEM  = 256L * 3 * 64 * 64;   // 3,145,728
static constexpr long  N4      = N_ELEM / 4;           // 786,432 float4

__global__ void init_accum_kernel() {
    g_accum[0] = 0.0;
    g_accum[1] = 0.0;
}

__device__ __forceinline__ float warp_reduce(float v) {
    #pragma unroll
    for (int off = 16; off > 0; off >>= 1)
        v += __shfl_xor_sync(0xFFFFFFFFu, v, off);
    return v;
}

// Fused: grid-stride MSE partial sums over all blocks; blocks 0..255 also
// handle one z-row each for the pairwise-cosine term.
__global__ void __launch_bounds__(256)
fused_reduce_kernel(const float4* __restrict__ y4,
                    const float4* __restrict__ x4,
                    const float*  __restrict__ z)
{
    const int tid  = threadIdx.x;
    const int lane = tid & 31;
    const int wid  = tid >> 5;

    __shared__ float s_mse[8];
    __shared__ float s_s2[8];
    __shared__ float s_s4[8];

    // ---- MSE part: grid-stride over float4 ----
    float acc = 0.0f;
    long stride = (long)gridDim.x * blockDim.x;
    for (long i = (long)blockIdx.x * blockDim.x + tid; i < N4; i += stride) {
        float4 a = y4[i];
        float4 b = x4[i];
        float d0 = a.x - b.x;
        float d1 = a.y - b.y;
        float d2 = a.z - b.z;
        float d3 = a.w - b.w;
        acc += d0 * d0 + d1 * d1 + d2 * d2 + d3 * d3;
    }
    acc = warp_reduce(acc);
    if (lane == 0) s_mse[wid] = acc;

    // ---- z part: one block per batch row (blocks 0..255) ----
    float s2 = 0.0f, s4 = 0.0f;
    if (blockIdx.x < B) {
        // 256 threads, 512 floats per row -> one float2 per thread
        const float2* zr = reinterpret_cast<const float2*>(z + (long)blockIdx.x * H);
        float2 v = zr[tid];
        float q0 = v.x * v.x;
        float q1 = v.y * v.y;
        s2 = q0 + q1;
        s4 = q0 * q0 + q1 * q1;
    }
    s2 = warp_reduce(s2);
    s4 = warp_reduce(s4);
    if (lane == 0) { s_s2[wid] = s2; s_s4[wid] = s4; }

    __syncthreads();

    if (wid == 0) {
        float m  = (lane < 8) ? s_mse[lane] : 0.0f;
        m = warp_reduce(m);
        if (lane == 0 && m != 0.0f)
            atomicAdd(&g_accum[0], (double)m);

        if (blockIdx.x < B) {
            float t2 = (lane < 8) ? s_s2[lane] : 0.0f;
            float t4 = (lane < 8) ? s_s4[lane] : 0.0f;
            t2 = warp_reduce(t2);
            t4 = warp_reduce(t4);
            if (lane == 0) {
                double d2 = (double)t2;
                double term = 1.0 - (double)t4 / (d2 * d2);
                atomicAdd(&g_accum[1], term);
            }
        }
    }
}

__global__ void finalize_kernel(float* __restrict__ out) {
    double mse = g_accum[0] / (double)N_ELEM;
    double pt  = g_accum[1] / ((double)B * (double)H * (double)H);
    out[0] = (float)(mse + 0.1 * pt);
}

extern "C" void kernel_launch(void* const* d_in, const int* in_sizes, int n_in,
                              void* d_out, int out_size)
{
    const float4* y4 = (const float4*)d_in[0];   // yhat_xhat
    const float4* x4 = (const float4*)d_in[1];   // xhat
    const float*  z  = (const float*)d_in[2];    // z_xhat
    float* out = (float*)d_out;

    init_accum_kernel<<<1, 1>>>();
    // 1024 blocks x 256 threads: >= 256 blocks (z rows), ~3 float4 pairs/thread
    fused_reduce_kernel<<<1024, 256>>>(y4, x4, z);
    finalize_kernel<<<1, 1>>>(out);
}

// round 2
// speedup vs baseline: 1.1831x; 1.1831x over previous
#include <cuda_runtime.h>

// Persistent device state (zero-initialized at module load; the last block
// of every launch resets it, so every graph replay starts from zero).
__device__ double       g_accum[2];  // [0] = sum sq-diff, [1] = sum over batch of (1 - s4/s2^2)
__device__ unsigned int g_count;     // block-arrival counter

static constexpr int  B      = 256;
static constexpr int  H      = 512;
static constexpr long N_ELEM = 256L * 3 * 64 * 64;   // 3,145,728
static constexpr long N4     = N_ELEM / 4;           // 786,432 float4
static constexpr int  GRID   = 1024;                 // >= B (z rows), 4 threads' worth per SM-wave
static constexpr int  TPB    = 256;

__device__ __forceinline__ float warp_reduce(float v) {
    #pragma unroll
    for (int off = 16; off > 0; off >>= 1)
        v += __shfl_xor_sync(0xFFFFFFFFu, v, off);
    return v;
}

__global__ void __launch_bounds__(TPB)
fused_loss_kernel(const float4* __restrict__ y4,
                  const float4* __restrict__ x4,
                  const float*  __restrict__ z,
                  float* __restrict__ out)
{
    const int tid  = threadIdx.x;
    const int lane = tid & 31;
    const int wid  = tid >> 5;

    __shared__ float s_mse[8];
    __shared__ float s_s2[8];
    __shared__ float s_s4[8];
    __shared__ bool  s_is_last;

    // ---- MSE part: grid-stride over float4 ----
    float acc = 0.0f;
    const long stride = (long)GRID * TPB;
    for (long i = (long)blockIdx.x * TPB + tid; i < N4; i += stride) {
        float4 a = y4[i];
        float4 b = x4[i];
        float d0 = a.x - b.x;
        float d1 = a.y - b.y;
        float d2 = a.z - b.z;
        float d3 = a.w - b.w;
        acc += d0 * d0 + d1 * d1 + d2 * d2 + d3 * d3;
    }
    acc = warp_reduce(acc);
    if (lane == 0) s_mse[wid] = acc;

    // ---- z part: blocks 0..255 each own one batch row (512 floats, 2/thread) ----
    float s2 = 0.0f, s4 = 0.0f;
    if (blockIdx.x < B) {
        const float2* zr = reinterpret_cast<const float2*>(z + (long)blockIdx.x * H);
        float2 v = zr[tid];
        float q0 = v.x * v.x;
        float q1 = v.y * v.y;
        s2 = q0 + q1;
        s4 = q0 * q0 + q1 * q1;
    }
    s2 = warp_reduce(s2);
    s4 = warp_reduce(s4);
    if (lane == 0) { s_s2[wid] = s2; s_s4[wid] = s4; }

    __syncthreads();

    // ---- block-level combine + global atomics ----
    if (wid == 0) {
        float m = (lane < 8) ? s_mse[lane] : 0.0f;
        m = warp_reduce(m);
        if (lane == 0)
            atomicAdd(&g_accum[0], (double)m);

        if (blockIdx.x < B) {
            float t2 = (lane < 8) ? s_s2[lane] : 0.0f;
            float t4 = (lane < 8) ? s_s4[lane] : 0.0f;
            t2 = warp_reduce(t2);
            t4 = warp_reduce(t4);
            if (lane == 0) {
                double d2 = (double)t2;
                atomicAdd(&g_accum[1], 1.0 - (double)t4 / (d2 * d2));
            }
        }
    }

    // ---- last block finalizes and resets state for the next replay ----
    if (tid == 0) {
        __threadfence();
        unsigned prev = atomicAdd(&g_count, 1u);
        s_is_last = (prev == (unsigned)(GRID - 1));
    }
    __syncthreads();

    if (s_is_last && tid == 0) {
        // atomicAdd(p, 0.0) forces an L2-coherent read of the accumulators
        double sum_sq = atomicAdd(&g_accum[0], 0.0);
        double sum_pt = atomicAdd(&g_accum[1], 0.0);

        double mse = sum_sq / (double)N_ELEM;
        double pt  = sum_pt / ((double)B * (double)H * (double)H);
        out[0] = (float)(mse + 0.1 * pt);

        // reset for next graph replay
        g_accum[0] = 0.0;
        g_accum[1] = 0.0;
        __threadfence();
        g_count = 0u;
    }
}

extern "C" void kernel_launch(void* const* d_in, const int* in_sizes, int n_in,
                              void* d_out, int out_size)
{
    const float4* y4 = (const float4*)d_in[0];   // yhat_xhat
    const float4* x4 = (const float4*)d_in[1];   // xhat
    const float*  z  = (const float*)d_in[2];    // z_xhat
    float* out = (float*)d_out;

    fused_loss_kernel<<<GRID, TPB>>>(y4, x4, z, out);
}

// round 3
// speedup vs baseline: 1.1866x; 1.0029x over previous
#include <cuda_runtime.h>

static constexpr int  B      = 256;
static constexpr int  H      = 512;
static constexpr long N_ELEM = 256L * 3 * 64 * 64;   // 3,145,728
static constexpr long N4     = N_ELEM / 4;           // 786,432 float4
static constexpr int  GRID   = 1024;
static constexpr int  TPB    = 256;
static constexpr int  ITERS  = (int)(N4 / ((long)GRID * TPB));  // == 3, exact

// Per-block partials (overwritten every launch before counter bump -> no init needed)
__device__ double       g_part_mse[GRID];
__device__ double       g_part_pt[B];
__device__ unsigned int g_count;   // zero-init at load; last block resets each launch

__device__ __forceinline__ float warp_reduce(float v) {
    #pragma unroll
    for (int off = 16; off > 0; off >>= 1)
        v += __shfl_xor_sync(0xFFFFFFFFu, v, off);
    return v;
}

__global__ void __launch_bounds__(TPB)
fused_loss_kernel(const float4* __restrict__ y4,
                  const float4* __restrict__ x4,
                  const float*  __restrict__ z,
                  float* __restrict__ out)
{
    const int tid  = threadIdx.x;
    const int lane = tid & 31;
    const int wid  = tid >> 5;

    __shared__ float s_mse[8];
    __shared__ float s_s2[8];
    __shared__ float s_s4[8];
    __shared__ bool  s_is_last;

    // ---- MSE: exactly ITERS float4-pairs per thread, fully unrolled so all
    //      2*ITERS LDG.128s are batched up front (high MLP) ----
    const long base   = (long)blockIdx.x * TPB + tid;
    const long stride = (long)GRID * TPB;

    float4 ya[ITERS], xa[ITERS];
    #pragma unroll
    for (int k = 0; k < ITERS; k++) ya[k] = y4[base + k * stride];
    #pragma unroll
    for (int k = 0; k < ITERS; k++) xa[k] = x4[base + k * stride];

    float acc = 0.0f;
    #pragma unroll
    for (int k = 0; k < ITERS; k++) {
        float d0 = ya[k].x - xa[k].x;
        float d1 = ya[k].y - xa[k].y;
        float d2 = ya[k].z - xa[k].z;
        float d3 = ya[k].w - xa[k].w;
        acc += d0 * d0 + d1 * d1 + d2 * d2 + d3 * d3;
    }
    acc = warp_reduce(acc);
    if (lane == 0) s_mse[wid] = acc;

    // ---- z term: blocks 0..255 each own one batch row (512 floats, 2/thread) ----
    float s2 = 0.0f, s4 = 0.0f;
    if (blockIdx.x < B) {
        const float2* zr = reinterpret_cast<const float2*>(z + (long)blockIdx.x * H);
        float2 v = zr[tid];
        float q0 = v.x * v.x;
        float q1 = v.y * v.y;
        s2 = q0 + q1;
        s4 = q0 * q0 + q1 * q1;
    }
    s2 = warp_reduce(s2);
    s4 = warp_reduce(s4);
    if (lane == 0) { s_s2[wid] = s2; s_s4[wid] = s4; }

    __syncthreads();

    // ---- block combine -> private partial slots (no contended atomics) ----
    if (wid == 0) {
        float m = (lane < 8) ? s_mse[lane] : 0.0f;
        m = warp_reduce(m);
        if (lane == 0) g_part_mse[blockIdx.x] = (double)m;

        if (blockIdx.x < B) {
            float t2 = (lane < 8) ? s_s2[lane] : 0.0f;
            float t4 = (lane < 8) ? s_s4[lane] : 0.0f;
            t2 = warp_reduce(t2);
            t4 = warp_reduce(t4);
            if (lane == 0) {
                double d2 = (double)t2;
                g_part_pt[blockIdx.x] = 1.0 - (double)t4 / (d2 * d2);
            }
        }
    }

    // ---- arrival counter; last block reduces the partials ----
    if (tid == 0) {
        __threadfence();
        unsigned prev = atomicAdd(&g_count, 1u);
        s_is_last = (prev == (unsigned)(GRID - 1));
    }
    __syncthreads();

    if (!s_is_last) return;

    // Last block: reduce GRID mse-partials + B pt-partials.
    __shared__ double sd_mse[8];
    __shared__ double sd_pt[8];

    double dm = 0.0;
    #pragma unroll
    for (int k = 0; k < GRID / TPB; k++)           // 4 per thread
        dm += __ldcg(&g_part_mse[tid + k * TPB]);

    double dp = (tid < B) ? __ldcg(&g_part_pt[tid]) : 0.0;

    #pragma unroll
    for (int off = 16; off > 0; off >>= 1) {
        dm += __shfl_xor_sync(0xFFFFFFFFu, dm, off);
        dp += __shfl_xor_sync(0xFFFFFFFFu, dp, off);
    }
    if (lane == 0) { sd_mse[wid] = dm; sd_pt[wid] = dp; }
    __syncthreads();

    if (tid == 0) {
        double sum_sq = 0.0, sum_pt = 0.0;
        #pragma unroll
        for (int w = 0; w < 8; w++) { sum_sq += sd_mse[w]; sum_pt += sd_pt[w]; }

        double mse = sum_sq / (double)N_ELEM;
        double pt  = sum_pt / ((double)B * (double)H * (double)H);
        out[0] = (float)(mse + 0.1 * pt);

        g_count = 0u;   // reset for next graph replay
    }
}

extern "C" void kernel_launch(void* const* d_in, const int* in_sizes, int n_in,
                              void* d_out, int out_size)
{
    const float4* y4 = (const float4*)d_in[0];   // yhat_xhat
    const float4* x4 = (const float4*)d_in[1];   // xhat
    const float*  z  = (const float*)d_in[2];    // z_xhat
    float* out = (float*)d_out;

    fused_loss_kernel<<<GRID, TPB>>>(y4, x4, z, out);
}